// round 1
// baseline (speedup 1.0000x reference)
#include <cuda_runtime.h>

#define MEM_M 131072
#define E 512

// ---- device scratch (no allocation allowed) ----
__device__ __align__(16) float g_kpart[3 * 16 * E];   // key GEMV partials
__device__ __align__(16) float g_rkeyn[E];            // r_key / ||r_key||
__device__ __align__(16) float g_wkeyn[E];            // w_key / ||w_key||
__device__ __align__(16) float g_erase[E];
__device__ __align__(16) float g_accA[E];             // sum sims_r * mem
__device__ __align__(16) float g_accB[E];             // sum sims_r * sims_w * mem
__device__ float g_S[2];                              // S_r, S_w
__device__ __align__(16) float g_opart[32 * E];       // output GEMV partials

// ============================================================
// K1: partial GEMVs  key[j] = sum_i x[i] * W[i][j]
// grid = 48 blocks: m = matrix (0=w_key,1=r_key,2=erase), c = 32-row chunk
// ============================================================
__global__ void k_gemv_keys(const float* __restrict__ x,
                            const float* __restrict__ wkg,
                            const float* __restrict__ weg,
                            const float* __restrict__ rkg) {
    const int bb = blockIdx.x;
    const int m = bb >> 4, c = bb & 15;
    const float* W = (m == 0) ? wkg : ((m == 1) ? rkg : weg);
    __shared__ float sx[32];
    const int j = threadIdx.x;  // 512 threads
    if (j < 32) sx[j] = x[c * 32 + j];
    __syncthreads();
    float p = 0.f;
#pragma unroll
    for (int i = 0; i < 32; i++)
        p += sx[i] * W[(c * 32 + i) * E + j];
    g_kpart[(m * 16 + c) * E + j] = p;
}

// ============================================================
// K2: reduce key partials, normalize keys by their L2 norm,
//     zero the main-pass accumulators.  1 block x 512 threads.
// ============================================================
__global__ void k_finalize_keys() {
    const int j = threadIdx.x;
    float kw = 0.f, kr = 0.f, ke = 0.f;
#pragma unroll
    for (int c = 0; c < 16; c++) {
        kw += g_kpart[(0 * 16 + c) * E + j];
        kr += g_kpart[(1 * 16 + c) * E + j];
        ke += g_kpart[(2 * 16 + c) * E + j];
    }
    g_erase[j] = ke;

    float w2 = kw * kw, r2 = kr * kr;
#pragma unroll
    for (int off = 16; off; off >>= 1) {
        w2 += __shfl_xor_sync(0xffffffffu, w2, off);
        r2 += __shfl_xor_sync(0xffffffffu, r2, off);
    }
    __shared__ float rw[16], rr[16];
    __shared__ float s_iw, s_ir;
    const int wid = j >> 5, lane = j & 31;
    if (lane == 0) { rw[wid] = w2; rr[wid] = r2; }
    __syncthreads();
    if (j == 0) {
        float a = 0.f, b = 0.f;
#pragma unroll
        for (int k = 0; k < 16; k++) { a += rw[k]; b += rr[k]; }
        s_iw = rsqrtf(a);
        s_ir = rsqrtf(b);
    }
    __syncthreads();
    g_wkeyn[j] = kw * s_iw;
    g_rkeyn[j] = kr * s_ir;
    g_accA[j] = 0.f;
    g_accB[j] = 0.f;
    if (j < 2) g_S[j] = 0.f;
}

// ============================================================
// K3: single pass over memory (256 MB).  One warp per row.
//   sims_r = <row, rkeyn> / ||row||,  sims_w = <row, wkeyn> / ||row||
//   accA += sims_r * row,  accB += sims_r*sims_w * row, S += sims
// ============================================================
#define DOT4(a, b) ((a).x*(b).x + (a).y*(b).y + (a).z*(b).z + (a).w*(b).w)
#define AXPY4(acc, s, v) do { (acc).x += (s)*(v).x; (acc).y += (s)*(v).y; \
                              (acc).z += (s)*(v).z; (acc).w += (s)*(v).w; } while (0)

__global__ void __launch_bounds__(256, 2) k_main(const float* __restrict__ mem) {
    __shared__ float4 shA[8][128];  // 16 KB
    __shared__ float4 shB[8][128];  // 16 KB
    __shared__ float sS[16];

    const int tid = threadIdx.x;
    const int w = tid >> 5, l = tid & 31;
    const int gw = blockIdx.x * 8 + w;
    const int nW = gridDim.x * 8;

    const float4* rk4 = (const float4*)g_rkeyn;
    const float4* wk4 = (const float4*)g_wkeyn;
    const float4 kr0 = rk4[l],      kr1 = rk4[32 + l], kr2 = rk4[64 + l], kr3 = rk4[96 + l];
    const float4 kw0 = wk4[l],      kw1 = wk4[32 + l], kw2 = wk4[64 + l], kw3 = wk4[96 + l];

    float4 a0 = make_float4(0, 0, 0, 0), a1 = a0, a2 = a0, a3 = a0;
    float4 b0 = a0, b1 = a0, b2 = a0, b3 = a0;
    float Sr = 0.f, Sw = 0.f;

    int row = gw;
    float4 v0 = a0, v1 = a0, v2 = a0, v3 = a0;
    if (row < MEM_M) {
        const float4* r4 = (const float4*)(mem + (size_t)row * E);
        v0 = r4[l]; v1 = r4[32 + l]; v2 = r4[64 + l]; v3 = r4[96 + l];
    }

    while (row < MEM_M) {
        const int nrow = row + nW;
        // prefetch next row (hides DRAM latency behind this row's compute)
        float4 p0 = v0, p1 = v1, p2 = v2, p3 = v3;
        if (nrow < MEM_M) {
            const float4* r4 = (const float4*)(mem + (size_t)nrow * E);
            p0 = r4[l]; p1 = r4[32 + l]; p2 = r4[64 + l]; p3 = r4[96 + l];
        }

        float dr = DOT4(v0, kr0) + DOT4(v1, kr1) + DOT4(v2, kr2) + DOT4(v3, kr3);
        float dw = DOT4(v0, kw0) + DOT4(v1, kw1) + DOT4(v2, kw2) + DOT4(v3, kw3);
        float nn = DOT4(v0, v0)  + DOT4(v1, v1)  + DOT4(v2, v2)  + DOT4(v3, v3);

#pragma unroll
        for (int off = 16; off; off >>= 1) {
            dr += __shfl_xor_sync(0xffffffffu, dr, off);
            dw += __shfl_xor_sync(0xffffffffu, dw, off);
            nn += __shfl_xor_sync(0xffffffffu, nn, off);
        }

        const float inv = rsqrtf(nn);
        const float sr = dr * inv;
        const float sw = dw * inv;
        const float srw = sr * sw;

        AXPY4(a0, sr, v0); AXPY4(a1, sr, v1); AXPY4(a2, sr, v2); AXPY4(a3, sr, v3);
        AXPY4(b0, srw, v0); AXPY4(b1, srw, v1); AXPY4(b2, srw, v2); AXPY4(b3, srw, v3);
        Sr += sr; Sw += sw;

        row = nrow;
        v0 = p0; v1 = p1; v2 = p2; v3 = p3;
    }

    // per-warp accumulators -> shared slices
    shA[w][l] = a0; shA[w][32 + l] = a1; shA[w][64 + l] = a2; shA[w][96 + l] = a3;
    shB[w][l] = b0; shB[w][32 + l] = b1; shB[w][64 + l] = b2; shB[w][96 + l] = b3;
    if (l == 0) { sS[w] = Sr; sS[8 + w] = Sw; }
    __syncthreads();

    const float* fA = (const float*)shA;
    const float* fB = (const float*)shB;
    for (int j = tid; j < E; j += 256) {
        float a = 0.f, b = 0.f;
#pragma unroll
        for (int k = 0; k < 8; k++) {
            a += fA[k * E + j];
            b += fB[k * E + j];
        }
        atomicAdd(&g_accA[j], a);
        atomicAdd(&g_accB[j], b);
    }
    if (tid == 0) {
        float r = 0.f, ww = 0.f;
#pragma unroll
        for (int k = 0; k < 8; k++) { r += sS[k]; ww += sS[8 + k]; }
        atomicAdd(&g_S[0], r);
        atomicAdd(&g_S[1], ww);
    }
}

// ============================================================
// K4: output GEMV partials  out[j] = sum_i c[i]*post[i][j],
//     c = concat(x0, r_vect).  32 blocks x 32 i-rows each.
// ============================================================
__global__ void k_out_part(const float* __restrict__ x,
                           const float* __restrict__ post) {
    __shared__ float sc[32];
    const int b = blockIdx.x, tid = threadIdx.x;
    const int i0 = b * 32;
    if (tid < 32) {
        const int i = i0 + tid;
        float ci;
        if (i < E) {
            ci = x[i];
        } else {
            const int e = i - E;
            const float Sr = g_S[0], Sw = g_S[1];
            ci = (g_accA[e] - g_erase[e] * g_accB[e] / Sw) / Sr;
        }
        sc[tid] = ci;
    }
    __syncthreads();
    for (int j = tid; j < E; j += 256) {
        float acc = 0.f;
#pragma unroll
        for (int i = 0; i < 32; i++)
            acc += sc[i] * post[(i0 + i) * E + j];
        g_opart[b * E + j] = acc;
    }
}

// ============================================================
// K5: reduce output partials -> d_out
// ============================================================
__global__ void k_out_final(float* __restrict__ out) {
    const int j = threadIdx.x;
    float s = 0.f;
#pragma unroll
    for (int b = 0; b < 32; b++) s += g_opart[b * E + j];
    out[j] = s;
}

// ============================================================
extern "C" void kernel_launch(void* const* d_in, const int* in_sizes, int n_in,
                              void* d_out, int out_size) {
    const float* x    = (const float*)d_in[0];
    const float* mem  = (const float*)d_in[1];
    const float* wkg  = (const float*)d_in[2];
    // d_in[3] = w_vect_gen: computed-but-unused in the reference (dead)
    const float* weg  = (const float*)d_in[4];
    const float* rkg  = (const float*)d_in[5];
    const float* post = (const float*)d_in[6];

    k_gemv_keys<<<48, 512>>>(x, wkg, weg, rkg);
    k_finalize_keys<<<1, 512>>>();
    k_main<<<296, 256>>>(mem);
    k_out_part<<<32, 256>>>(x, post);
    k_out_final<<<1, 512>>>((float*)d_out);
}

// round 2
// speedup vs baseline: 1.0372x; 1.0372x over previous
#include <cuda_runtime.h>

#define MEM_M 131072
#define E 512

// ---- device scratch (no allocation allowed) ----
__device__ __align__(16) float g_kpart[3 * 32 * E];   // key GEMV partials
__device__ __align__(16) float g_rkeyn[E];            // r_key / ||r_key||
__device__ __align__(16) float g_wkeyn[E];            // w_key / ||w_key||
__device__ __align__(16) float g_erase[E];
__device__ __align__(16) float g_accA[E];             // sum sims_r * mem
__device__ __align__(16) float g_accB[E];             // sum sims_r * sims_w * mem
__device__ float g_S[2];                              // S_r, S_w
__device__ __align__(16) float g_opart[128 * E];      // output GEMV partials

// ============================================================
// K1: partial GEMVs  key[j] = sum_i x[i] * W[i][j]
// grid = 96 blocks: m = matrix (0=w_key,1=r_key,2=erase), c = 16-row chunk
// 512 threads, one output column each, 16 rows per chunk.
// ============================================================
__global__ void k_gemv_keys(const float* __restrict__ x,
                            const float* __restrict__ wkg,
                            const float* __restrict__ weg,
                            const float* __restrict__ rkg) {
    const int bb = blockIdx.x;
    const int m = bb >> 5, c = bb & 31;
    const float* W = (m == 0) ? wkg : ((m == 1) ? rkg : weg);
    __shared__ float sx[16];
    const int j = threadIdx.x;  // 512 threads
    if (j < 16) sx[j] = x[c * 16 + j];
    __syncthreads();
    float p = 0.f;
#pragma unroll
    for (int i = 0; i < 16; i++)
        p += sx[i] * W[(c * 16 + i) * E + j];
    g_kpart[(m * 32 + c) * E + j] = p;
}

// ============================================================
// K2: reduce key partials, normalize keys by their L2 norm,
//     zero the main-pass accumulators.  1 block x 512 threads.
// ============================================================
__global__ void k_finalize_keys() {
    const int j = threadIdx.x;
    float kw = 0.f, kr = 0.f, ke = 0.f;
#pragma unroll
    for (int c = 0; c < 32; c++) {
        kw += g_kpart[(0 * 32 + c) * E + j];
        kr += g_kpart[(1 * 32 + c) * E + j];
        ke += g_kpart[(2 * 32 + c) * E + j];
    }
    g_erase[j] = ke;

    float w2 = kw * kw, r2 = kr * kr;
#pragma unroll
    for (int off = 16; off; off >>= 1) {
        w2 += __shfl_xor_sync(0xffffffffu, w2, off);
        r2 += __shfl_xor_sync(0xffffffffu, r2, off);
    }
    __shared__ float rw[16], rr[16];
    __shared__ float s_iw, s_ir;
    const int wid = j >> 5, lane = j & 31;
    if (lane == 0) { rw[wid] = w2; rr[wid] = r2; }
    __syncthreads();
    if (j == 0) {
        float a = 0.f, b = 0.f;
#pragma unroll
        for (int k = 0; k < 16; k++) { a += rw[k]; b += rr[k]; }
        s_iw = rsqrtf(a);
        s_ir = rsqrtf(b);
    }
    __syncthreads();
    g_wkeyn[j] = kw * s_iw;
    g_rkeyn[j] = kr * s_ir;
    g_accA[j] = 0.f;
    g_accB[j] = 0.f;
    if (j < 2) g_S[j] = 0.f;
}

// ============================================================
// K3: single pass over memory (256 MB).  One warp per row.
//   sims_r = <row, rkeyn> / ||row||,  sims_w = <row, wkeyn> / ||row||
//   accA += sims_r * row,  accB += sims_r*sims_w * row, S += sims
// ============================================================
#define DOT4(a, b) ((a).x*(b).x + (a).y*(b).y + (a).z*(b).z + (a).w*(b).w)
#define AXPY4(acc, s, v) do { (acc).x += (s)*(v).x; (acc).y += (s)*(v).y; \
                              (acc).z += (s)*(v).z; (acc).w += (s)*(v).w; } while (0)

__global__ void __launch_bounds__(256, 2) k_main(const float* __restrict__ mem) {
    __shared__ float4 shA[8][128];  // 16 KB
    __shared__ float4 shB[8][128];  // 16 KB
    __shared__ float sS[16];

    const int tid = threadIdx.x;
    const int w = tid >> 5, l = tid & 31;
    const int gw = blockIdx.x * 8 + w;
    const int nW = gridDim.x * 8;

    const float4* rk4 = (const float4*)g_rkeyn;
    const float4* wk4 = (const float4*)g_wkeyn;
    const float4 kr0 = rk4[l],      kr1 = rk4[32 + l], kr2 = rk4[64 + l], kr3 = rk4[96 + l];
    const float4 kw0 = wk4[l],      kw1 = wk4[32 + l], kw2 = wk4[64 + l], kw3 = wk4[96 + l];

    float4 a0 = make_float4(0, 0, 0, 0), a1 = a0, a2 = a0, a3 = a0;
    float4 b0 = a0, b1 = a0, b2 = a0, b3 = a0;
    float Sr = 0.f, Sw = 0.f;

    int row = gw;
    float4 v0 = a0, v1 = a0, v2 = a0, v3 = a0;
    if (row < MEM_M) {
        const float4* r4 = (const float4*)(mem + (size_t)row * E);
        v0 = __ldcs(r4 + l);      v1 = __ldcs(r4 + 32 + l);
        v2 = __ldcs(r4 + 64 + l); v3 = __ldcs(r4 + 96 + l);
    }

    while (row < MEM_M) {
        const int nrow = row + nW;
        // prefetch next row (hides DRAM latency behind this row's compute)
        float4 p0 = v0, p1 = v1, p2 = v2, p3 = v3;
        if (nrow < MEM_M) {
            const float4* r4 = (const float4*)(mem + (size_t)nrow * E);
            p0 = __ldcs(r4 + l);      p1 = __ldcs(r4 + 32 + l);
            p2 = __ldcs(r4 + 64 + l); p3 = __ldcs(r4 + 96 + l);
        }

        float dr = DOT4(v0, kr0) + DOT4(v1, kr1) + DOT4(v2, kr2) + DOT4(v3, kr3);
        float dw = DOT4(v0, kw0) + DOT4(v1, kw1) + DOT4(v2, kw2) + DOT4(v3, kw3);
        float nn = DOT4(v0, v0)  + DOT4(v1, v1)  + DOT4(v2, v2)  + DOT4(v3, v3);

#pragma unroll
        for (int off = 16; off; off >>= 1) {
            dr += __shfl_xor_sync(0xffffffffu, dr, off);
            dw += __shfl_xor_sync(0xffffffffu, dw, off);
            nn += __shfl_xor_sync(0xffffffffu, nn, off);
        }

        const float inv = rsqrtf(nn);
        const float sr = dr * inv;
        const float sw = dw * inv;
        const float srw = sr * sw;

        AXPY4(a0, sr, v0); AXPY4(a1, sr, v1); AXPY4(a2, sr, v2); AXPY4(a3, sr, v3);
        AXPY4(b0, srw, v0); AXPY4(b1, srw, v1); AXPY4(b2, srw, v2); AXPY4(b3, srw, v3);
        Sr += sr; Sw += sw;

        row = nrow;
        v0 = p0; v1 = p1; v2 = p2; v3 = p3;
    }

    // per-warp accumulators -> shared slices
    shA[w][l] = a0; shA[w][32 + l] = a1; shA[w][64 + l] = a2; shA[w][96 + l] = a3;
    shB[w][l] = b0; shB[w][32 + l] = b1; shB[w][64 + l] = b2; shB[w][96 + l] = b3;
    if (l == 0) { sS[w] = Sr; sS[8 + w] = Sw; }
    __syncthreads();

    const float* fA = (const float*)shA;
    const float* fB = (const float*)shB;
    for (int j = tid; j < E; j += 256) {
        float a = 0.f, b = 0.f;
#pragma unroll
        for (int k = 0; k < 8; k++) {
            a += fA[k * E + j];
            b += fB[k * E + j];
        }
        atomicAdd(&g_accA[j], a);
        atomicAdd(&g_accB[j], b);
    }
    if (tid == 0) {
        float r = 0.f, ww = 0.f;
#pragma unroll
        for (int k = 0; k < 8; k++) { r += sS[k]; ww += sS[8 + k]; }
        atomicAdd(&g_S[0], r);
        atomicAdd(&g_S[1], ww);
    }
}

// ============================================================
// K4: output GEMV partials  out[j] = sum_i c[i]*post[i][j],
//     c = concat(x0, r_vect).  128 blocks x 8 i-rows each.
// ============================================================
__global__ void k_out_part(const float* __restrict__ x,
                           const float* __restrict__ post) {
    __shared__ float sc[8];
    const int b = blockIdx.x, tid = threadIdx.x;
    const int i0 = b * 8;
    if (tid < 8) {
        const int i = i0 + tid;
        float ci;
        if (i < E) {
            ci = x[i];
        } else {
            const int e = i - E;
            const float Sr = g_S[0], Sw = g_S[1];
            ci = (g_accA[e] - g_erase[e] * g_accB[e] / Sw) / Sr;
        }
        sc[tid] = ci;
    }
    __syncthreads();
#pragma unroll
    for (int jj = 0; jj < 2; jj++) {
        const int j = tid + jj * 256;
        float acc = 0.f;
#pragma unroll
        for (int i = 0; i < 8; i++)
            acc += sc[i] * post[(i0 + i) * E + j];
        g_opart[b * E + j] = acc;
    }
}

// ============================================================
// K5: reduce output partials -> d_out.  128 threads x float4.
// ============================================================
__global__ void k_out_final(float* __restrict__ out) {
    const int t = threadIdx.x;  // 128 threads, one float4 column each
    const float4* p4 = (const float4*)g_opart;
    float4 s = make_float4(0, 0, 0, 0);
#pragma unroll
    for (int b = 0; b < 128; b++) {
        float4 v = p4[b * 128 + t];
        s.x += v.x; s.y += v.y; s.z += v.z; s.w += v.w;
    }
    ((float4*)out)[t] = s;
}

// ============================================================
extern "C" void kernel_launch(void* const* d_in, const int* in_sizes, int n_in,
                              void* d_out, int out_size) {
    const float* x    = (const float*)d_in[0];
    const float* mem  = (const float*)d_in[1];
    const float* wkg  = (const float*)d_in[2];
    // d_in[3] = w_vect_gen: computed-but-unused in the reference (dead)
    const float* weg  = (const float*)d_in[4];
    const float* rkg  = (const float*)d_in[5];
    const float* post = (const float*)d_in[6];

    k_gemv_keys<<<96, 512>>>(x, wkg, weg, rkg);
    k_finalize_keys<<<1, 512>>>();
    k_main<<<296, 256>>>(mem);
    k_out_part<<<128, 256>>>(x, post);
    k_out_final<<<1, 128>>>((float*)d_out);
}

// round 4
// speedup vs baseline: 1.1416x; 1.1007x over previous
#include <cuda_runtime.h>

#define MEM_M 131072
#define E 512

typedef unsigned long long u64;

// ---- device scratch (no allocation allowed) ----
__device__ __align__(16) float g_kpart[3 * 64 * E];   // key GEMV partials
__device__ __align__(16) float g_rkeyn[E];            // r_key / ||r_key||
__device__ __align__(16) float g_wkeyn[E];            // w_key / ||w_key||
__device__ __align__(16) float g_erase[E];
__device__ __align__(16) float g_accA[E];             // sum sims_r * mem
__device__ __align__(16) float g_accB[E];             // sum sims_r * sims_w * mem
__device__ float g_S[2];                              // S_r, S_w

__device__ __forceinline__ float warp_sum(float v) {
#pragma unroll
    for (int o = 16; o; o >>= 1) v += __shfl_xor_sync(0xffffffffu, v, o);
    return v;
}

// ---- packed f32x2 helpers (sm_103a native FFMA2) ----
__device__ __forceinline__ u64 pk2(float lo, float hi) {
    u64 r; asm("mov.b64 %0, {%1, %2};" : "=l"(r) : "f"(lo), "f"(hi)); return r;
}
__device__ __forceinline__ float hadd2(u64 v) {
    float lo, hi; asm("mov.b64 {%0, %1}, %2;" : "=f"(lo), "=f"(hi) : "l"(v));
    return lo + hi;
}
__device__ __forceinline__ u64 fma2(u64 a, u64 b, u64 c) {
    u64 r; asm("fma.rn.f32x2 %0, %1, %2, %3;" : "=l"(r) : "l"(a), "l"(b), "l"(c));
    return r;
}

// ============================================================
// K1: partial GEMVs  key[j] = sum_i x[i] * W[i][j]
// grid = 192: m = matrix (0=w_key,1=r_key,2=erase), c = 8-row chunk
// ============================================================
__global__ void k_gemv_keys(const float* __restrict__ x,
                            const float* __restrict__ wkg,
                            const float* __restrict__ weg,
                            const float* __restrict__ rkg) {
    const int bb = blockIdx.x;
    const int m = bb >> 6, c = bb & 63;
    const float* W = (m == 0) ? wkg : ((m == 1) ? rkg : weg);
    __shared__ float sx[8];
    const int j = threadIdx.x;  // 512 threads
    if (j < 8) sx[j] = x[c * 8 + j];
    __syncthreads();
    float p = 0.f;
#pragma unroll
    for (int i = 0; i < 8; i++)
        p += sx[i] * W[(c * 8 + i) * E + j];
    g_kpart[(m * 64 + c) * E + j] = p;
}

// ============================================================
// K2: reduce key partials, normalize keys, zero accumulators + out
// ============================================================
__global__ void k_finalize_keys(float* __restrict__ out) {
    const int j = threadIdx.x;  // 512
    float kw = 0.f, kr = 0.f, ke = 0.f;
#pragma unroll
    for (int c = 0; c < 64; c++) {
        kw += g_kpart[(0 * 64 + c) * E + j];
        kr += g_kpart[(1 * 64 + c) * E + j];
        ke += g_kpart[(2 * 64 + c) * E + j];
    }
    g_erase[j] = ke;

    float w2 = warp_sum(kw * kw);
    float r2 = warp_sum(kr * kr);
    __shared__ float rw[16], rr[16];
    __shared__ float s_iw, s_ir;
    const int wid = j >> 5, lane = j & 31;
    if (lane == 0) { rw[wid] = w2; rr[wid] = r2; }
    __syncthreads();
    if (j == 0) {
        float a = 0.f, b = 0.f;
#pragma unroll
        for (int k = 0; k < 16; k++) { a += rw[k]; b += rr[k]; }
        s_iw = rsqrtf(a);
        s_ir = rsqrtf(b);
    }
    __syncthreads();
    g_wkeyn[j] = kw * s_iw;
    g_rkeyn[j] = kr * s_ir;
    g_accA[j] = 0.f;
    g_accB[j] = 0.f;
    out[j] = 0.f;           // K4 accumulates into d_out via atomics
    if (j < 2) g_S[j] = 0.f;
}

// ============================================================
// K3: single pass over memory (256 MB).  One warp per row.
// All heavy math in packed f32x2 (FFMA2): 40 packed FMA per row
// instead of 80 scalar -> fma pipe no longer binds, DRAM does.
// ============================================================
#define PROCESS_ROW(V) do {                                                     \
    u64 dr2 = 0ull, dw2 = 0ull, nn2 = 0ull;                                     \
    _Pragma("unroll")                                                           \
    for (int i = 0; i < 8; i++) {                                               \
        dr2 = fma2(V[i], kr[i], dr2);                                           \
        dw2 = fma2(V[i], kw[i], dw2);                                           \
        nn2 = fma2(V[i], V[i], nn2);                                            \
    }                                                                           \
    float dr = hadd2(dr2), dw = hadd2(dw2), nn = hadd2(nn2);                    \
    _Pragma("unroll")                                                           \
    for (int o = 16; o; o >>= 1) {                                              \
        dr += __shfl_xor_sync(0xffffffffu, dr, o);                              \
        dw += __shfl_xor_sync(0xffffffffu, dw, o);                              \
        nn += __shfl_xor_sync(0xffffffffu, nn, o);                              \
    }                                                                           \
    const float inv = rsqrtf(nn);                                               \
    const float sr = dr * inv;                                                  \
    const float sw = dw * inv;                                                  \
    const float srw = sr * sw;                                                  \
    const u64 sr2 = pk2(sr, sr), srw2 = pk2(srw, srw);                          \
    _Pragma("unroll")                                                           \
    for (int i = 0; i < 8; i++) {                                               \
        acA[i] = fma2(V[i], sr2, acA[i]);                                       \
        acB[i] = fma2(V[i], srw2, acB[i]);                                      \
    }                                                                           \
    Sr += sr; Sw += sw;                                                         \
} while (0)

__global__ void __launch_bounds__(256, 2) k_main(const float* __restrict__ mem) {
    __shared__ u64 shA[8][256];  // 16 KB
    __shared__ u64 shB[8][256];  // 16 KB
    __shared__ float sS[16];

    const int tid = threadIdx.x;
    const int w = tid >> 5, l = tid & 31;
    const int gw = blockIdx.x * 8 + w;
    const int nW = gridDim.x * 8;

    // lane l handles packed elements {2i*32+? } : key layout matches row loads:
    // u64 index within the 256-u64 row: chunk i in [0,8), position i*32 + l... 
    // row float4 q at index (i/2)*32 + l -> u64s 2*((i/2)*32+l) + (i&1).
    u64 kr[8], kw[8];
    {
        const u64* rk = (const u64*)g_rkeyn;
        const u64* wk = (const u64*)g_wkeyn;
#pragma unroll
        for (int q = 0; q < 4; q++) {
            kr[2 * q]     = rk[(q * 32 + l) * 2];
            kr[2 * q + 1] = rk[(q * 32 + l) * 2 + 1];
            kw[2 * q]     = wk[(q * 32 + l) * 2];
            kw[2 * q + 1] = wk[(q * 32 + l) * 2 + 1];
        }
    }

    u64 acA[8], acB[8];
#pragma unroll
    for (int i = 0; i < 8; i++) { acA[i] = 0ull; acB[i] = 0ull; }
    float Sr = 0.f, Sw = 0.f;

    const int iters = (MEM_M - 1 - gw) / nW + 1;
    const float4* ptr = (const float4*)mem + (size_t)gw * 128 + l;
    const size_t stride = (size_t)nW * 128;

    u64 v[8], p[8];
#pragma unroll
    for (int q = 0; q < 4; q++) {
        float4 t = __ldcs(ptr + q * 32);
        v[2 * q]     = ((u64*)&t)[0];
        v[2 * q + 1] = ((u64*)&t)[1];
    }

    for (int it = 1; it < iters; ++it) {
        ptr += stride;
#pragma unroll
        for (int q = 0; q < 4; q++) {
            float4 t = __ldcs(ptr + q * 32);
            p[2 * q]     = ((u64*)&t)[0];
            p[2 * q + 1] = ((u64*)&t)[1];
        }
        PROCESS_ROW(v);
#pragma unroll
        for (int i = 0; i < 8; i++) v[i] = p[i];
    }
    PROCESS_ROW(v);

    // per-warp accumulators -> shared slices (same packed layout)
#pragma unroll
    for (int q = 0; q < 4; q++) {
        shA[w][(q * 32 + l) * 2]     = acA[2 * q];
        shA[w][(q * 32 + l) * 2 + 1] = acA[2 * q + 1];
        shB[w][(q * 32 + l) * 2]     = acB[2 * q];
        shB[w][(q * 32 + l) * 2 + 1] = acB[2 * q + 1];
    }
    if (l == 0) { sS[w] = Sr; sS[8 + w] = Sw; }
    __syncthreads();

    const float* fA = (const float*)shA;
    const float* fB = (const float*)shB;
    for (int j = tid; j < E; j += 256) {
        float a = 0.f, b = 0.f;
#pragma unroll
        for (int k = 0; k < 8; k++) {
            a += fA[k * E + j];
            b += fB[k * E + j];
        }
        atomicAdd(&g_accA[j], a);
        atomicAdd(&g_accB[j], b);
    }
    if (tid == 0) {
        float r = 0.f, ww = 0.f;
#pragma unroll
        for (int k = 0; k < 8; k++) { r += sS[k]; ww += sS[8 + k]; }
        atomicAdd(&g_S[0], r);
        atomicAdd(&g_S[1], ww);
    }
}

// ============================================================
// K4: output GEMV, atomics into d_out (zeroed by K2).
// grid 128 x 128 threads; block b handles rows [8b, 8b+8).
// ============================================================
__global__ void k_out(const float* __restrict__ x,
                      const float* __restrict__ post,
                      float* __restrict__ out) {
    __shared__ float sc[8];
    const int b = blockIdx.x, t = threadIdx.x;
    const int i0 = b * 8;
    if (t < 8) {
        const int i = i0 + t;
        float ci;
        if (i < E) {
            ci = x[i];
        } else {
            const int e = i - E;
            ci = (g_accA[e] - g_erase[e] * g_accB[e] / g_S[1]) / g_S[0];
        }
        sc[t] = ci;
    }
    __syncthreads();
    const float4* p4 = (const float4*)post;
    float4 acc = make_float4(0, 0, 0, 0);
#pragma unroll
    for (int i = 0; i < 8; i++) {
        float4 v = p4[(size_t)(i0 + i) * 128 + t];
        acc.x += sc[i] * v.x; acc.y += sc[i] * v.y;
        acc.z += sc[i] * v.z; acc.w += sc[i] * v.w;
    }
    atomicAdd(&out[4 * t + 0], acc.x);
    atomicAdd(&out[4 * t + 1], acc.y);
    atomicAdd(&out[4 * t + 2], acc.z);
    atomicAdd(&out[4 * t + 3], acc.w);
}

// ============================================================
extern "C" void kernel_launch(void* const* d_in, const int* in_sizes, int n_in,
                              void* d_out, int out_size) {
    const float* x    = (const float*)d_in[0];
    const float* mem  = (const float*)d_in[1];
    const float* wkg  = (const float*)d_in[2];
    // d_in[3] = w_vect_gen: computed-but-unused in the reference (dead)
    const float* weg  = (const float*)d_in[4];
    const float* rkg  = (const float*)d_in[5];
    const float* post = (const float*)d_in[6];

    k_gemv_keys<<<192, 512>>>(x, wkg, weg, rkg);
    k_finalize_keys<<<1, 512>>>((float*)d_out);
    k_main<<<296, 256>>>(mem);
    k_out<<<128, 128>>>(x, post, (float*)d_out);
}